// round 1
// baseline (speedup 1.0000x reference)
#include <cuda_runtime.h>

#define Bv 64
#define Tv 2048
#define Cv 1
#define Nv 128

// One CTA per (batch, conjugate). Thread n owns output tag n.
// State kept in scaled linear space: W[n] = exp(alpha[n] - L).
// Per step: s[n] = sum_j W[j] * E[j][n]  (E = exp(transitions), in registers),
//           W'[n] = s[n] * exp(em_t[n]) * (1/r),  L += log(r),  r = W_prev[0].
__global__ __launch_bounds__(Nv, 1)
void crf_fwd(const float* __restrict__ emissions,
             const int* __restrict__ token_sizes,
             const float* __restrict__ transitions,
             const float* __restrict__ head,
             const float* __restrict__ last,
             float* __restrict__ out)
{
    const int bc = blockIdx.x;
    const int b = bc / Cv;
    const int c = bc % Cv;
    const int n = threadIdx.x;

    __shared__ __align__(16) float W[2][Nv];
    __shared__ float red[4];

    // Column n of exp(transitions[c]) lives in registers (128 regs).
    // Loop over j gives coalesced loads (lane n -> trans[j*Nv + n]).
    float e[Nv];
    const float* tr = transitions + (size_t)c * Nv * Nv;
    #pragma unroll
    for (int j = 0; j < Nv; ++j)
        e[j] = __expf(tr[j * Nv + n]);

    const int len = token_sizes[b];
    const float* em = emissions + (((size_t)b * Tv) * Cv + c) * Nv + n;
    const size_t ts = (size_t)Cv * Nv;  // element stride between timesteps

    // t = 0: alpha0 = head + em[0]; enter linear space normalized by K = alpha0[0].
    float a0 = head[c * Nv + n] + em[0];
    W[0][n] = a0;
    __syncthreads();
    float K = W[0][0];
    float logM = K;
    W[1][n] = __expf(a0 - K);
    __syncthreads();
    int p = 1;

    // Distance-2 emission prefetch pipeline (load-to-use ~2 steps > DRAM lat).
    float ex_cur = __expf(em[1 * ts]);                  // exp(em) for t = 1
    float em_n2  = em[(size_t)min(2, Tv - 1) * ts];     // em for t = 2

    for (int t = 1; t < len; ++t) {
        float r = W[p][0];                 // broadcast LDS; normalizer from prev step
        float inv_r = __frcp_rn(r);
        logM += __logf(r);                 // off critical path

        // 128-tap dot product, 4 accumulators to keep FMA dep chain < issue floor.
        float s0 = 0.f, s1 = 0.f, s2 = 0.f, s3 = 0.f;
        #pragma unroll
        for (int j = 0; j < Nv; j += 4) {
            float4 w4 = *reinterpret_cast<const float4*>(&W[p][j]);  // broadcast LDS.128
            s0 = fmaf(w4.x, e[j + 0], s0);
            s1 = fmaf(w4.y, e[j + 1], s1);
            s2 = fmaf(w4.z, e[j + 2], s2);
            s3 = fmaf(w4.w, e[j + 3], s3);
        }
        float s = (s0 + s1) + (s2 + s3);
        W[p ^ 1][n] = s * (ex_cur * inv_r);

        // advance emission pipeline (clamped index stays in-bounds; value unused past len)
        ex_cur = __expf(em_n2);
        em_n2  = em[(size_t)min(t + 2, Tv - 1) * ts];

        __syncthreads();                   // single barrier per step (double buffer)
        p ^= 1;
    }

    // Finalize: out = logM + log(sum_n W[n] * exp(last[n]))
    float term = W[p][n] * __expf(last[c * Nv + n]);
    #pragma unroll
    for (int o = 16; o > 0; o >>= 1)
        term += __shfl_down_sync(0xffffffffu, term, o);
    if ((n & 31) == 0) red[n >> 5] = term;
    __syncthreads();
    if (n == 0) {
        float tot = (red[0] + red[1]) + (red[2] + red[3]);
        out[bc] = logM + logf(tot);
    }
}

extern "C" void kernel_launch(void* const* d_in, const int* in_sizes, int n_in,
                              void* d_out, int out_size) {
    const float* emissions   = (const float*)d_in[0];
    const int*   token_sizes = (const int*)d_in[1];
    const float* transitions = (const float*)d_in[2];
    const float* head        = (const float*)d_in[3];
    const float* last        = (const float*)d_in[4];
    crf_fwd<<<Bv * Cv, Nv>>>(emissions, token_sizes, transitions, head, last,
                             (float*)d_out);
}

// round 3
// speedup vs baseline: 1.2077x; 1.2077x over previous
#include <cuda_runtime.h>

#define Bv 64
#define Tv 2048
#define Cv 1
#define Nv 128

__device__ __forceinline__ void ffma2(unsigned long long& d,
                                      unsigned long long a,
                                      unsigned long long b) {
    asm("fma.rn.f32x2 %0, %1, %2, %0;" : "+l"(d) : "l"(a), "l"(b));
}
__device__ __forceinline__ void fadd2(unsigned long long& d, unsigned long long a) {
    asm("add.rn.f32x2 %0, %0, %1;" : "+l"(d) : "l"(a));
}
__device__ __forceinline__ unsigned long long pack2(float a, float b) {
    unsigned long long r;
    asm("mov.b64 %0, {%1, %2};" : "=l"(r) : "f"(a), "f"(b));
    return r;
}
__device__ __forceinline__ float2 unpack2(unsigned long long v) {
    float2 r;
    asm("mov.b64 {%0, %1}, %2;" : "=f"(r.x), "=f"(r.y) : "l"(v));
    return r;
}
__device__ __forceinline__ float lo32(unsigned long long v) {
    float r;
    asm("{ .reg .f32 hi; mov.b64 {%0, hi}, %1; }" : "=f"(r) : "l"(v));
    return r;
}

// One CTA per (batch, conjugate); thread n owns output tag n.
// Scaled linear space: alpha_t[n] = logM + log(W_t[n]).
// Per step: s[n] = sum_j W[j]*E[j][n] (E = exp(trans), packed f32x2 in regs),
//           W'[n] = s[n] * exp(em_t[n]) * inv_r,  logM += k*ln2,
// where inv_r = 2^-k is the power-of-2 magnitude of W_prev[0] (exact rescale,
// integer-only, no MUFU on the critical path).
__global__ __launch_bounds__(Nv, 1)
void crf_fwd(const float* __restrict__ emissions,
             const int* __restrict__ token_sizes,
             const float* __restrict__ transitions,
             const float* __restrict__ head,
             const float* __restrict__ last,
             float* __restrict__ out)
{
    const int bc = blockIdx.x;
    const int b = bc / Cv;
    const int c = bc % Cv;
    const int n = threadIdx.x;

    __shared__ __align__(16) float W[2][Nv];
    __shared__ float red[4];

    // Pack column n of exp(transitions[c]) as 64 f32x2 register pairs.
    unsigned long long e2[Nv / 2];
    const float* tr = transitions + (size_t)c * Nv * Nv;
    #pragma unroll
    for (int k = 0; k < Nv / 2; ++k) {
        float lo = __expf(tr[(2 * k + 0) * Nv + n]);
        float hi = __expf(tr[(2 * k + 1) * Nv + n]);
        e2[k] = pack2(lo, hi);
    }

    const int len = token_sizes[b];
    const float* em = emissions + (((size_t)b * Tv) * Cv + c) * Nv + n;
    const int ts = Cv * Nv;  // element stride between timesteps

    // t = 0: alpha0 = head + em[0]; normalize by K = alpha0[0].
    float a0 = head[c * Nv + n] + em[0];
    W[0][n] = a0;
    __syncthreads();
    float K = W[0][0];
    float logM = K;
    W[1][n] = __expf(a0 - K);
    __syncthreads();
    int p = 1;

    // Distance-2 emission prefetch (index-clamped; clamped value unused past len).
    float ex_cur = __expf(em[1 * ts]);                  // exp(em) for t = 1
    float em_n2  = em[min(2, Tv - 1) * ts];             // em for t = 2

    for (int t = 1; t < len; ++t) {
        const ulonglong2* Wv = reinterpret_cast<const ulonglong2*>(W[p]);

        // Peel k = 0: first LDS.128 also yields w0 = W[p][0] for the rescale.
        ulonglong2 w = Wv[0];
        float w0 = lo32(w.x);
        unsigned long long s0 = 0ull, s1 = 0ull, s2 = 0ull, s3 = 0ull;
        ffma2(s0, w.x, e2[0]);
        ffma2(s1, w.y, e2[1]);

        #pragma unroll
        for (int k = 1; k < Nv / 4; ++k) {              // 31 more LDS.128, 62 FFMA2
            w = Wv[k];
            if ((k & 1) == 0) { ffma2(s0, w.x, e2[2 * k]); ffma2(s1, w.y, e2[2 * k + 1]); }
            else              { ffma2(s2, w.x, e2[2 * k]); ffma2(s3, w.y, e2[2 * k + 1]); }
        }
        fadd2(s0, s1); fadd2(s2, s3); fadd2(s0, s2);
        float2 sp = unpack2(s0);
        float s = sp.x + sp.y;

        // Exact power-of-2 rescale from previous W[0]'s exponent (no MUFU).
        int ebits = __float_as_int(w0) & 0x7f800000;
        float inv_r = __int_as_float(0x7f000000 - ebits);      // 2^(127 - E)
        logM += (float)((ebits >> 23) - 127) * 0.693147180559945f;

        W[p ^ 1][n] = s * (ex_cur * inv_r);

        // Advance emission pipeline.
        ex_cur = __expf(em_n2);
        em_n2  = em[min(t + 2, Tv - 1) * ts];

        __syncthreads();
        p ^= 1;
    }

    // Finalize: out = logM + log(sum_n W[n] * exp(last[n]))
    float term = W[p][n] * __expf(last[c * Nv + n]);
    #pragma unroll
    for (int o = 16; o > 0; o >>= 1)
        term += __shfl_down_sync(0xffffffffu, term, o);
    if ((n & 31) == 0) red[n >> 5] = term;
    __syncthreads();
    if (n == 0) {
        float tot = (red[0] + red[1]) + (red[2] + red[3]);
        out[bc] = logM + logf(tot);
    }
}

extern "C" void kernel_launch(void* const* d_in, const int* in_sizes, int n_in,
                              void* d_out, int out_size) {
    const float* emissions   = (const float*)d_in[0];
    const int*   token_sizes = (const int*)d_in[1];
    const float* transitions = (const float*)d_in[2];
    const float* head        = (const float*)d_in[3];
    const float* last        = (const float*)d_in[4];
    crf_fwd<<<Bv * Cv, Nv>>>(emissions, token_sizes, transitions, head, last,
                             (float*)d_out);
}